// round 15
// baseline (speedup 1.0000x reference)
#include <cuda_runtime.h>
#include <cuda_fp16.h>
#include <math.h>
#include <stdint.h>

#define TOK   2048
#define HD    1024
#define ID    1024
#define NE    32
#define TOPK  4
#define TWOI  2048
#define PAIRS (TOK*TOPK)
#define LIMITF 7.0f
#define ALPHAF 1.702f

// -------- device scratch --------
__device__ int    g_count[NE];
__device__ int    g_offset[NE];
__device__ int    g_cursor[NE];
__device__ int    g_topk_idx[TOK * TOPK];
__device__ float  g_topk_w[TOK * TOPK];
__device__ int    g_pair_token[PAIRS];
__device__ int    g_pair_of[TOK * TOPK];
__device__ __half g_xh[(size_t)PAIRS * HD];    // gathered fp16 token rows (16MB)
__device__ __half g_acth[(size_t)PAIRS * ID];  // fp16 activated intermediate (16MB)
__device__ float  g_y[(size_t)PAIRS * HD];     // down GEMM output (32MB)

// -------- helpers --------
__device__ __forceinline__ void mma_f16(float* d, const uint32_t* a, const uint32_t* b) {
    asm volatile(
        "mma.sync.aligned.m16n8k16.row.col.f32.f16.f16.f32 "
        "{%0,%1,%2,%3}, {%4,%5,%6,%7}, {%8,%9}, {%0,%1,%2,%3};\n"
        : "+f"(d[0]), "+f"(d[1]), "+f"(d[2]), "+f"(d[3])
        : "r"(a[0]), "r"(a[1]), "r"(a[2]), "r"(a[3]),
          "r"(b[0]), "r"(b[1]));
}
__device__ __forceinline__ uint32_t h2u(__half2 h) { return *(uint32_t*)&h; }
__device__ __forceinline__ void cp16(void* s, const void* g) {
    unsigned sa = (unsigned)__cvta_generic_to_shared(s);
    asm volatile("cp.async.cg.shared.global [%0], [%1], 16;\n" :: "r"(sa), "l"(g));
}
#define CP_COMMIT() asm volatile("cp.async.commit_group;\n" ::: "memory")
#define CP_WAIT2()  asm volatile("cp.async.wait_group 2;\n" ::: "memory")

// dynamic smem layout:
//   A: 4 stages x [128][40] halves = 4 x 10240 B = 40960 B
//   B: 4 stages x [32][132] fp32  = 4 x 16896 B = 67584 B
#define A_STAGE_H 5120              // halves per A stage
#define B_STAGE_F 4224              // floats per B stage
#define B_BASE_BYTES 40960
#define SMEM_BYTES 108544

// -------- grouped fp16 GEMM, 256 thr, 128x128 tile, BK=32, all-cp.async --------
// FIRST:  A = g_xh rows,   W = gate_up (ldb=2048), out = g_acth (fused act, fp16)
// !FIRST: A = g_acth rows, W = down    (ldb=1024), out = g_y (fp32)
template<bool FIRST>
__global__ __launch_bounds__(256, 2) void moe_gemm(const float* __restrict__ W,
                                                   const float* __restrict__ gub) {
    const int LDBW = FIRST ? TWOI : HD;
    const int bx = blockIdx.x;
    const int e  = blockIdx.y >> 4;
    const int rt = blockIdx.y & 15;
    const int base = g_offset[e];
    const int cnt  = g_count[e];
    const int row0 = rt * 128;
    if (row0 >= cnt) return;

    extern __shared__ __align__(16) char smem[];
    __half* Ah = (__half*)smem;
    float*  Bf = (float*)(smem + B_BASE_BYTES);

    const int tid  = threadIdx.x;
    const int lane = tid & 31;
    const int wid  = tid >> 5;
    const int wm   = wid >> 2;         // 0..1
    const int wn   = wid & 3;          // 0..3
    const int lr   = lane >> 2;        // 0..7
    const int lc   = lane & 3;         // 0..3

    // A cp.async: thread -> (row tid>>1, 16-half chunk (tid&1)), 2x 16B per stage
    const int rowA = tid >> 1;
    const int chA  = (tid & 1) * 16;   // half offset within 32-half k-tile
    int ar = row0 + rowA; if (ar >= cnt) ar = cnt - 1;
    const __half* aSrc = (FIRST ? (const __half*)g_xh : (const __half*)g_acth)
                         + (size_t)(base + ar) * 1024 + chA;
    const int aDst = rowA * 40 + chA;  // half index within stage

    // B cp.async: thread -> (k row tid>>3 of 32, col chunk (tid&7)*16), 4x 16B per stage
    const int rB = tid >> 3;           // 0..31
    const int cB = (tid & 7) * 16;     // 0..112
    const float* bSrc = W + ((size_t)e * 1024 + rB) * LDBW + bx * 128 + cB;
    const int bDst = rB * 132 + cB;    // float index within stage

    float acc[4][4][4];
    #pragma unroll
    for (int i = 0; i < 4; i++)
        #pragma unroll
        for (int j = 0; j < 4; j++)
            #pragma unroll
            for (int q = 0; q < 4; q++) acc[i][j][q] = 0.f;

    const int NK = 32;   // 1024/32

    // ---- prologue: issue stages 0..2 ----
    #pragma unroll
    for (int s = 0; s < 3; s++) {
        const __half* ag = aSrc + s * 32;
        __half* ad = Ah + s * A_STAGE_H + aDst;
        cp16(ad,     ag);
        cp16(ad + 8, ag + 8);
        const float* bg = bSrc + (size_t)s * 32 * LDBW;
        float* bd = Bf + s * B_STAGE_F + bDst;
        #pragma unroll
        for (int j = 0; j < 4; j++) cp16(bd + j * 4, bg + j * 4);
        CP_COMMIT();
    }

    #pragma unroll 1
    for (int kt = 0; kt < NK; kt++) {
        CP_WAIT2();            // stage kt complete (3 groups in flight)
        __syncthreads();

        const __half* Ab = Ah + (kt & 3) * A_STAGE_H;
        const float*  Bb = Bf + (kt & 3) * B_STAGE_F;

        #pragma unroll
        for (int kk = 0; kk < 2; kk++) {
            // B fragments: fp32 loads + pack (conflict-free banks)
            uint32_t bf[4][2];
            #pragma unroll
            for (int nt = 0; nt < 4; nt++) {
                const int n = wn * 32 + nt * 8 + lr;
                float b00 = Bb[(kk * 16 + 2 * lc) * 132 + n];
                float b01 = Bb[(kk * 16 + 2 * lc + 1) * 132 + n];
                float b10 = Bb[(kk * 16 + 2 * lc + 8) * 132 + n];
                float b11 = Bb[(kk * 16 + 2 * lc + 9) * 132 + n];
                bf[nt][0] = h2u(__floats2half2_rn(b00, b01));
                bf[nt][1] = h2u(__floats2half2_rn(b10, b11));
            }
            #pragma unroll
            for (int mt = 0; mt < 4; mt++) {
                const int r = wm * 64 + mt * 16 + lr;
                uint32_t af[4];
                af[0] = *(const uint32_t*)&Ab[r * 40 + kk * 16 + 2 * lc];
                af[1] = *(const uint32_t*)&Ab[(r + 8) * 40 + kk * 16 + 2 * lc];
                af[2] = *(const uint32_t*)&Ab[r * 40 + kk * 16 + 2 * lc + 8];
                af[3] = *(const uint32_t*)&Ab[(r + 8) * 40 + kk * 16 + 2 * lc + 8];
                #pragma unroll
                for (int nt = 0; nt < 4; nt++)
                    mma_f16(acc[mt][nt], af, bf[nt]);
            }
        }

        // issue stage kt+3 (lands in the buffer consumed at kt-1; safe post-sync)
        if (kt + 3 < NK) {
            const __half* ag = aSrc + (kt + 3) * 32;
            __half* ad = Ah + ((kt + 3) & 3) * A_STAGE_H + aDst;
            cp16(ad,     ag);
            cp16(ad + 8, ag + 8);
            const float* bg = bSrc + (size_t)(kt + 3) * 32 * LDBW;
            float* bd = Bf + ((kt + 3) & 3) * B_STAGE_F + bDst;
            #pragma unroll
            for (int j = 0; j < 4; j++) cp16(bd + j * 4, bg + j * 4);
        }
        CP_COMMIT();
    }

    // ---- epilogue ----
    if (FIRST) {
        const float* gb = gub + (size_t)e * TWOI;
        #pragma unroll
        for (int mt = 0; mt < 4; mt++) {
            #pragma unroll
            for (int half = 0; half < 2; half++) {
                const int grow = row0 + wm * 64 + mt * 16 + lr + half * 8;
                if (grow < cnt) {
                    __half* orow = g_acth + (size_t)(base + grow) * ID;
                    #pragma unroll
                    for (int nt = 0; nt < 4; nt++) {
                        const int i = bx * 64 + wn * 16 + nt * 4 + lc;
                        float gate = acc[mt][nt][half * 2 + 0] + gb[2 * i];
                        float up   = acc[mt][nt][half * 2 + 1] + gb[2 * i + 1];
                        gate = fminf(gate, LIMITF);
                        up   = fminf(fmaxf(up, -LIMITF), LIMITF);
                        float glu = gate / (1.f + __expf(-gate * ALPHAF));
                        orow[i] = __float2half((up + 1.f) * glu);
                    }
                }
            }
        }
    } else {
        #pragma unroll
        for (int mt = 0; mt < 4; mt++) {
            #pragma unroll
            for (int half = 0; half < 2; half++) {
                const int grow = row0 + wm * 64 + mt * 16 + lr + half * 8;
                if (grow < cnt) {
                    float* orow = g_y + (size_t)(base + grow) * HD;
                    #pragma unroll
                    for (int nt = 0; nt < 4; nt++) {
                        const int c = bx * 128 + wn * 32 + nt * 8 + 2 * lc;
                        *(float2*)(orow + c) = make_float2(acc[mt][nt][half * 2 + 0],
                                                           acc[mt][nt][half * 2 + 1]);
                    }
                }
            }
        }
    }
}

// -------- K0: reset counters --------
__global__ void reset_kernel() {
    int i = threadIdx.x;
    if (i < NE) g_count[i] = 0;
}

// -------- K1: router --------
__global__ void router_kernel(const float* __restrict__ x,
                              const float* __restrict__ rw,
                              const float* __restrict__ rb,
                              float* __restrict__ scores_out) {
    const int t    = blockIdx.x;
    const int tid  = threadIdx.x;
    const int warp = tid >> 5;
    const int lane = tid & 31;

    __shared__ float logits[NE];
    const float* xr = x + (size_t)t * HD;

    for (int e = warp; e < NE; e += 8) {
        const float* w = rw + (size_t)e * HD;
        float s = 0.f;
        for (int h = lane; h < HD; h += 32) s += xr[h] * w[h];
        #pragma unroll
        for (int off = 16; off; off >>= 1) s += __shfl_down_sync(0xffffffffu, s, off);
        if (lane == 0) logits[e] = s + rb[e];
    }
    __syncthreads();

    if (warp == 0) {
        float cur = logits[lane];
        float sel_val[TOPK];
        int   sel_idx[TOPK];
        #pragma unroll
        for (int k = 0; k < TOPK; k++) {
            float bv = cur; int bi = lane;
            #pragma unroll
            for (int off = 16; off; off >>= 1) {
                float ov = __shfl_xor_sync(0xffffffffu, bv, off);
                int   oi = __shfl_xor_sync(0xffffffffu, bi, off);
                if (ov > bv || (ov == bv && oi < bi)) { bv = ov; bi = oi; }
            }
            sel_val[k] = bv; sel_idx[k] = bi;
            if (lane == bi) cur = -1e30f;
        }
        float m = sel_val[0];
        float ex[TOPK]; float sum = 0.f;
        #pragma unroll
        for (int k = 0; k < TOPK; k++) { ex[k] = expf(sel_val[k] - m); sum += ex[k]; }
        float inv = 1.f / sum;

        float sc = 0.f;
        #pragma unroll
        for (int k = 0; k < TOPK; k++) if (lane == sel_idx[k]) sc = ex[k] * inv;
        scores_out[(size_t)t * NE + lane] = sc;

        if (lane < TOPK) {
            g_topk_idx[t * TOPK + lane] = sel_idx[lane];
            g_topk_w[t * TOPK + lane]   = ex[lane] * inv;
            atomicAdd(&g_count[sel_idx[lane]], 1);
        }
    }
}

// -------- K2: prefix sum --------
__global__ void prefix_kernel() {
    if (threadIdx.x == 0) {
        int acc = 0;
        for (int e = 0; e < NE; e++) {
            g_offset[e] = acc;
            g_cursor[e] = acc;
            acc += g_count[e];
        }
    }
}

// -------- K3: scatter --------
__global__ void scatter_kernel() {
    int t = blockIdx.x * blockDim.x + threadIdx.x;
    if (t >= TOK) return;
    #pragma unroll
    for (int k = 0; k < TOPK; k++) {
        int e   = g_topk_idx[t * TOPK + k];
        int pos = atomicAdd(&g_cursor[e], 1);
        g_pair_token[pos] = t;
        g_pair_of[t * TOPK + k] = pos;
    }
}

// -------- K4: gather + fp32->fp16 convert of token rows --------
__global__ void xgather_kernel(const float* __restrict__ x) {
    const int p   = blockIdx.x;          // pair index
    const int tid = threadIdx.x;         // 128 threads, 8 elems each
    const float* src = x + (size_t)g_pair_token[p] * HD + tid * 8;
    __half* dst = g_xh + (size_t)p * HD + tid * 8;
    float4 v0 = *(const float4*)src;
    float4 v1 = *(const float4*)(src + 4);
    uint4 u;
    u.x = h2u(__floats2half2_rn(v0.x, v0.y));
    u.y = h2u(__floats2half2_rn(v0.z, v0.w));
    u.z = h2u(__floats2half2_rn(v1.x, v1.y));
    u.w = h2u(__floats2half2_rn(v1.z, v1.w));
    *(uint4*)dst = u;
}

// -------- K7: weighted combine + down bias --------
__global__ void combine_kernel(const float* __restrict__ db,
                               float* __restrict__ out) {
    size_t idx = (size_t)blockIdx.x * blockDim.x + threadIdx.x;
    if (idx >= (size_t)TOK * HD) return;
    int t = (int)(idx >> 10);
    int h = (int)(idx & 1023);
    float s = 0.f;
    #pragma unroll
    for (int k = 0; k < TOPK; k++) {
        int   p = g_pair_of[t * TOPK + k];
        int   e = g_topk_idx[t * TOPK + k];
        float w = g_topk_w[t * TOPK + k];
        s += w * (g_y[(size_t)p * HD + h] + db[(size_t)e * HD + h]);
    }
    out[(size_t)t * HD + h] = s;
}

// -------- launch --------
extern "C" void kernel_launch(void* const* d_in, const int* in_sizes, int n_in,
                              void* d_out, int out_size) {
    const float* hidden  = (const float*)d_in[0];
    const float* gate_up = (const float*)d_in[1];
    const float* gub     = (const float*)d_in[2];
    const float* down    = (const float*)d_in[3];
    const float* db      = (const float*)d_in[4];
    const float* rw      = (const float*)d_in[5];
    const float* rb      = (const float*)d_in[6];

    float* out_routed = (float*)d_out;
    float* out_scores = (float*)d_out + (size_t)TOK * HD;

    // one-time opt-in for >48KB dynamic smem (runs on the correctness call,
    // never during graph capture — same pattern that passed in round 4)
    static bool attr_done = false;
    if (!attr_done) {
        cudaFuncSetAttribute(moe_gemm<true>,  cudaFuncAttributeMaxDynamicSharedMemorySize, SMEM_BYTES);
        cudaFuncSetAttribute(moe_gemm<false>, cudaFuncAttributeMaxDynamicSharedMemorySize, SMEM_BYTES);
        attr_done = true;
    }

    reset_kernel<<<1, 32>>>();
    router_kernel<<<TOK, 256>>>(hidden, rw, rb, out_scores);
    prefix_kernel<<<1, 32>>>();
    scatter_kernel<<<(TOK + 255) / 256, 256>>>();
    xgather_kernel<<<PAIRS, 128>>>(hidden);

    moe_gemm<true><<<dim3(16, NE * 16), 256, SMEM_BYTES>>>(gate_up, gub);
    moe_gemm<false><<<dim3(8, NE * 16), 256, SMEM_BYTES>>>(down, nullptr);
    combine_kernel<<<((size_t)TOK * HD + 255) / 256, 256>>>(db, out_routed);
}

// round 16
// speedup vs baseline: 1.1293x; 1.1293x over previous
#include <cuda_runtime.h>
#include <cuda_fp16.h>
#include <math.h>
#include <stdint.h>

#define TOK   2048
#define HD    1024
#define ID    1024
#define NE    32
#define TOPK  4
#define TWOI  2048
#define PAIRS (TOK*TOPK)
#define LIMITF 7.0f
#define ALPHAF 1.702f

// -------- device scratch --------
__device__ int    g_count[NE];
__device__ int    g_offset[NE];
__device__ int    g_cursor[NE];
__device__ int    g_topk_idx[TOK * TOPK];
__device__ float  g_topk_w[TOK * TOPK];
__device__ int    g_pair_token[PAIRS];
__device__ int    g_pair_of[TOK * TOPK];
__device__ __half g_xh[(size_t)PAIRS * HD];    // gathered fp16 token rows (16MB)
__device__ __half g_acth[(size_t)PAIRS * ID];  // fp16 activated intermediate (16MB)
__device__ float  g_y[(size_t)PAIRS * HD];     // down GEMM output (32MB)

// -------- helpers --------
__device__ __forceinline__ void mma_f16(float* d, const uint32_t* a, const uint32_t* b) {
    asm volatile(
        "mma.sync.aligned.m16n8k16.row.col.f32.f16.f16.f32 "
        "{%0,%1,%2,%3}, {%4,%5,%6,%7}, {%8,%9}, {%0,%1,%2,%3};\n"
        : "+f"(d[0]), "+f"(d[1]), "+f"(d[2]), "+f"(d[3])
        : "r"(a[0]), "r"(a[1]), "r"(a[2]), "r"(a[3]),
          "r"(b[0]), "r"(b[1]));
}
__device__ __forceinline__ uint32_t h2u(__half2 h) { return *(uint32_t*)&h; }
__device__ __forceinline__ void cp16(void* s, const void* g) {
    unsigned sa = (unsigned)__cvta_generic_to_shared(s);
    asm volatile("cp.async.cg.shared.global [%0], [%1], 16;\n" :: "r"(sa), "l"(g));
}
#define CP_COMMIT() asm volatile("cp.async.commit_group;\n" ::: "memory")
#define CP_WAIT2()  asm volatile("cp.async.wait_group 2;\n" ::: "memory")

// -------- grouped fp16 GEMM, 256 thr, 128x128 tile, BK=16 (R13 structure) --------
// A: fp16 smem [2][128][24], double-buffered via register staging from fp16 GMEM.
// B: fp32 smem [4][16][132] via 4-stage cp.async ring; pack to fp16 at frag load.
// FIRST:  A = g_xh rows,   W = gate_up (ldb=2048), out = g_acth (fused act, fp16)
// !FIRST: A = g_acth rows, W = down    (ldb=1024), out = g_y (fp32)
template<bool FIRST>
__global__ __launch_bounds__(256, 2) void moe_gemm(const float* __restrict__ W,
                                                   const float* __restrict__ gub) {
    const int LDBW = FIRST ? TWOI : HD;
    const int bx = blockIdx.x;
    const int e  = blockIdx.y >> 4;
    const int rt = blockIdx.y & 15;
    const int base = g_offset[e];
    const int cnt  = g_count[e];
    const int row0 = rt * 128;
    if (row0 >= cnt) return;

    __shared__ __align__(16) __half As[2][128][24];
    __shared__ __align__(16) float  Bsf[4][16][132];

    const int tid  = threadIdx.x;
    const int lane = tid & 31;
    const int wid  = tid >> 5;
    const int wm   = wid >> 2;         // 0..1
    const int wn   = wid & 3;          // 0..3
    const int lr   = lane >> 2;        // 0..7
    const int lc   = lane & 3;         // 0..3

    // A staging: thread -> (m row tid>>1, k-half (tid&1)*8 halves): 1 LDG.128/STS.128
    const int rowA  = tid >> 1;
    const int halfA = (tid & 1) * 8;
    int ar = row0 + rowA; if (ar >= cnt) ar = cnt - 1;
    const __half* aSrc = (FIRST ? (const __half*)g_xh : (const __half*)g_acth)
                         + (size_t)(base + ar) * 1024 + halfA;

    // B staging via cp.async: thread -> (k row tid>>4, col chunk (tid&15)*8), 2x 16B
    const int rB = tid >> 4;           // 0..15
    const int cB = (tid & 15) * 8;     // 0..120
    const float* bSrc = W + ((size_t)e * 1024 + rB) * LDBW + bx * 128 + cB;

    float acc[4][4][4];
    #pragma unroll
    for (int i = 0; i < 4; i++)
        #pragma unroll
        for (int j = 0; j < 4; j++)
            #pragma unroll
            for (int q = 0; q < 4; q++) acc[i][j][q] = 0.f;

    const int NK = 64;   // 1024/16

    // ---- prologue: issue B stages 0..2; stage A tile 0 ----
    #pragma unroll
    for (int s = 0; s < 3; s++) {
        const float* src = bSrc + (size_t)s * 16 * LDBW;
        cp16(&Bsf[s][rB][cB],     src);
        cp16(&Bsf[s][rB][cB + 4], src + 4);
        CP_COMMIT();
    }
    *(uint4*)&As[0][rowA][halfA] = *(const uint4*)aSrc;

    #pragma unroll 1
    for (int kt = 0; kt < NK; kt++) {
        // A register prefetch for kt+1 (LDG overlapped with wait + compute)
        uint4 apf;
        if (kt + 1 < NK) apf = *(const uint4*)(aSrc + (kt + 1) * 16);

        CP_WAIT2();            // B stage kt complete (3 groups in flight)
        __syncthreads();

        const int ab = kt & 1;
        const int bs = kt & 3;

        // B fragments: fp32 loads + pack (conflict-free banks)
        uint32_t bf[4][2];
        #pragma unroll
        for (int nt = 0; nt < 4; nt++) {
            const int n = wn * 32 + nt * 8 + lr;
            float b00 = Bsf[bs][2 * lc][n];
            float b01 = Bsf[bs][2 * lc + 1][n];
            float b10 = Bsf[bs][2 * lc + 8][n];
            float b11 = Bsf[bs][2 * lc + 9][n];
            bf[nt][0] = h2u(__floats2half2_rn(b00, b01));
            bf[nt][1] = h2u(__floats2half2_rn(b10, b11));
        }
        #pragma unroll
        for (int mt = 0; mt < 4; mt++) {
            const int r = wm * 64 + mt * 16 + lr;
            uint32_t af[4];
            af[0] = *(const uint32_t*)&As[ab][r][2 * lc];
            af[1] = *(const uint32_t*)&As[ab][r + 8][2 * lc];
            af[2] = *(const uint32_t*)&As[ab][r][2 * lc + 8];
            af[3] = *(const uint32_t*)&As[ab][r + 8][2 * lc + 8];
            #pragma unroll
            for (int nt = 0; nt < 4; nt++)
                mma_f16(acc[mt][nt], af, bf[nt]);
        }

        // stage A(kt+1) into the alternate buffer (not read this iteration)
        if (kt + 1 < NK)
            *(uint4*)&As[(kt + 1) & 1][rowA][halfA] = apf;

        // issue B stage kt+3 (buffer last consumed at kt-1; safe post-sync)
        if (kt + 3 < NK) {
            const float* src = bSrc + (size_t)(kt + 3) * 16 * LDBW;
            cp16(&Bsf[(kt + 3) & 3][rB][cB],     src);
            cp16(&Bsf[(kt + 3) & 3][rB][cB + 4], src + 4);
        }
        CP_COMMIT();
    }

    // ---- epilogue ----
    if (FIRST) {
        const float* gb = gub + (size_t)e * TWOI;
        #pragma unroll
        for (int mt = 0; mt < 4; mt++) {
            #pragma unroll
            for (int half = 0; half < 2; half++) {
                const int grow = row0 + wm * 64 + mt * 16 + lr + half * 8;
                if (grow < cnt) {
                    __half* orow = g_acth + (size_t)(base + grow) * ID;
                    #pragma unroll
                    for (int nt = 0; nt < 4; nt++) {
                        const int i = bx * 64 + wn * 16 + nt * 4 + lc;
                        float gate = acc[mt][nt][half * 2 + 0] + gb[2 * i];
                        float up   = acc[mt][nt][half * 2 + 1] + gb[2 * i + 1];
                        gate = fminf(gate, LIMITF);
                        up   = fminf(fmaxf(up, -LIMITF), LIMITF);
                        float glu = gate / (1.f + __expf(-gate * ALPHAF));
                        orow[i] = __float2half((up + 1.f) * glu);
                    }
                }
            }
        }
    } else {
        #pragma unroll
        for (int mt = 0; mt < 4; mt++) {
            #pragma unroll
            for (int half = 0; half < 2; half++) {
                const int grow = row0 + wm * 64 + mt * 16 + lr + half * 8;
                if (grow < cnt) {
                    float* orow = g_y + (size_t)(base + grow) * HD;
                    #pragma unroll
                    for (int nt = 0; nt < 4; nt++) {
                        const int c = bx * 128 + wn * 32 + nt * 8 + 2 * lc;
                        *(float2*)(orow + c) = make_float2(acc[mt][nt][half * 2 + 0],
                                                           acc[mt][nt][half * 2 + 1]);
                    }
                }
            }
        }
    }
}

// -------- K0: reset counters --------
__global__ void reset_kernel() {
    int i = threadIdx.x;
    if (i < NE) g_count[i] = 0;
}

// -------- K1: router (4 tokens per block -> 4x less rw traffic) --------
__global__ __launch_bounds__(256) void router_kernel(const float* __restrict__ x,
                                                     const float* __restrict__ rw,
                                                     const float* __restrict__ rb,
                                                     float* __restrict__ scores_out) {
    const int t0   = blockIdx.x * 4;
    const int tid  = threadIdx.x;
    const int warp = tid >> 5;
    const int lane = tid & 31;

    __shared__ float xs[4][HD];        // 16KB: 4 token rows
    __shared__ float logits[4][NE];

    // load 4 token rows: 1024 float4, 4 per thread
    #pragma unroll
    for (int j = 0; j < 4; j++) {
        const int f   = tid * 4 + j;           // float4 index 0..1023
        const int row = f >> 8;
        const int col = (f & 255) * 4;
        *(float4*)&xs[row][col] = *(const float4*)(x + (size_t)(t0 + row) * HD + col);
    }
    __syncthreads();

    // each warp computes 4 experts x 4 tokens
    for (int e = warp; e < NE; e += 8) {
        const float* w = rw + (size_t)e * HD;
        float s0 = 0.f, s1 = 0.f, s2 = 0.f, s3 = 0.f;
        for (int h = lane; h < HD; h += 32) {
            float wv = w[h];
            s0 += xs[0][h] * wv;
            s1 += xs[1][h] * wv;
            s2 += xs[2][h] * wv;
            s3 += xs[3][h] * wv;
        }
        #pragma unroll
        for (int off = 16; off; off >>= 1) {
            s0 += __shfl_down_sync(0xffffffffu, s0, off);
            s1 += __shfl_down_sync(0xffffffffu, s1, off);
            s2 += __shfl_down_sync(0xffffffffu, s2, off);
            s3 += __shfl_down_sync(0xffffffffu, s3, off);
        }
        if (lane == 0) {
            float b = rb[e];
            logits[0][e] = s0 + b;
            logits[1][e] = s1 + b;
            logits[2][e] = s2 + b;
            logits[3][e] = s3 + b;
        }
    }
    __syncthreads();

    // warps 0..3: top-4 + softmax for token t0+warp
    if (warp < 4) {
        const int t = t0 + warp;
        float cur = logits[warp][lane];
        float sel_val[TOPK];
        int   sel_idx[TOPK];
        #pragma unroll
        for (int k = 0; k < TOPK; k++) {
            float bv = cur; int bi = lane;
            #pragma unroll
            for (int off = 16; off; off >>= 1) {
                float ov = __shfl_xor_sync(0xffffffffu, bv, off);
                int   oi = __shfl_xor_sync(0xffffffffu, bi, off);
                if (ov > bv || (ov == bv && oi < bi)) { bv = ov; bi = oi; }
            }
            sel_val[k] = bv; sel_idx[k] = bi;
            if (lane == bi) cur = -1e30f;
        }
        float m = sel_val[0];
        float ex[TOPK]; float sum = 0.f;
        #pragma unroll
        for (int k = 0; k < TOPK; k++) { ex[k] = expf(sel_val[k] - m); sum += ex[k]; }
        float inv = 1.f / sum;

        float sc = 0.f;
        #pragma unroll
        for (int k = 0; k < TOPK; k++) if (lane == sel_idx[k]) sc = ex[k] * inv;
        scores_out[(size_t)t * NE + lane] = sc;

        if (lane < TOPK) {
            g_topk_idx[t * TOPK + lane] = sel_idx[lane];
            g_topk_w[t * TOPK + lane]   = ex[lane] * inv;
            atomicAdd(&g_count[sel_idx[lane]], 1);
        }
    }
}

// -------- K2: prefix sum --------
__global__ void prefix_kernel() {
    if (threadIdx.x == 0) {
        int acc = 0;
        for (int e = 0; e < NE; e++) {
            g_offset[e] = acc;
            g_cursor[e] = acc;
            acc += g_count[e];
        }
    }
}

// -------- K3: scatter --------
__global__ void scatter_kernel() {
    int t = blockIdx.x * blockDim.x + threadIdx.x;
    if (t >= TOK) return;
    #pragma unroll
    for (int k = 0; k < TOPK; k++) {
        int e   = g_topk_idx[t * TOPK + k];
        int pos = atomicAdd(&g_cursor[e], 1);
        g_pair_token[pos] = t;
        g_pair_of[t * TOPK + k] = pos;
    }
}

// -------- K4: gather + fp32->fp16 convert of token rows --------
__global__ void xgather_kernel(const float* __restrict__ x) {
    const int p   = blockIdx.x;          // pair index
    const int tid = threadIdx.x;         // 128 threads, 8 elems each
    const float* src = x + (size_t)g_pair_token[p] * HD + tid * 8;
    __half* dst = g_xh + (size_t)p * HD + tid * 8;
    float4 v0 = *(const float4*)src;
    float4 v1 = *(const float4*)(src + 4);
    uint4 u;
    u.x = h2u(__floats2half2_rn(v0.x, v0.y));
    u.y = h2u(__floats2half2_rn(v0.z, v0.w));
    u.z = h2u(__floats2half2_rn(v1.x, v1.y));
    u.w = h2u(__floats2half2_rn(v1.z, v1.w));
    *(uint4*)dst = u;
}

// -------- K7: weighted combine + down bias --------
__global__ void combine_kernel(const float* __restrict__ db,
                               float* __restrict__ out) {
    size_t idx = (size_t)blockIdx.x * blockDim.x + threadIdx.x;
    if (idx >= (size_t)TOK * HD) return;
    int t = (int)(idx >> 10);
    int h = (int)(idx & 1023);
    float s = 0.f;
    #pragma unroll
    for (int k = 0; k < TOPK; k++) {
        int   p = g_pair_of[t * TOPK + k];
        int   e = g_topk_idx[t * TOPK + k];
        float w = g_topk_w[t * TOPK + k];
        s += w * (g_y[(size_t)p * HD + h] + db[(size_t)e * HD + h]);
    }
    out[(size_t)t * HD + h] = s;
}

// -------- launch --------
extern "C" void kernel_launch(void* const* d_in, const int* in_sizes, int n_in,
                              void* d_out, int out_size) {
    const float* hidden  = (const float*)d_in[0];
    const float* gate_up = (const float*)d_in[1];
    const float* gub     = (const float*)d_in[2];
    const float* down    = (const float*)d_in[3];
    const float* db      = (const float*)d_in[4];
    const float* rw      = (const float*)d_in[5];
    const float* rb      = (const float*)d_in[6];

    float* out_routed = (float*)d_out;
    float* out_scores = (float*)d_out + (size_t)TOK * HD;

    reset_kernel<<<1, 32>>>();
    router_kernel<<<TOK / 4, 256>>>(hidden, rw, rb, out_scores);
    prefix_kernel<<<1, 32>>>();
    scatter_kernel<<<(TOK + 255) / 256, 256>>>();
    xgather_kernel<<<PAIRS, 128>>>(hidden);

    moe_gemm<true><<<dim3(16, NE * 16), 256>>>(gate_up, gub);
    moe_gemm<false><<<dim3(8, NE * 16), 256>>>(down, nullptr);
    combine_kernel<<<((size_t)TOK * HD + 255) / 256, 256>>>(db, out_routed);
}